// round 6
// baseline (speedup 1.0000x reference)
#include <cuda_runtime.h>
#include <cuda_bf16.h>

#define N_NODES 1024

typedef unsigned long long u64;

// ---------------- packed f32x2 helpers (sm_103a) ----------------
__device__ __forceinline__ u64 pack2(float lo, float hi) {
    u64 r; asm("mov.b64 %0, {%1, %2};" : "=l"(r) : "f"(lo), "f"(hi)); return r;
}
__device__ __forceinline__ void unpack2(u64 v, float& lo, float& hi) {
    asm("mov.b64 {%0, %1}, %2;" : "=f"(lo), "=f"(hi) : "l"(v));
}
__device__ __forceinline__ u64 ffma2(u64 a, u64 b, u64 c) {
    u64 d; asm("fma.rn.f32x2 %0, %1, %2, %3;" : "=l"(d) : "l"(a), "l"(b), "l"(c)); return d;
}
__device__ __forceinline__ u64 add2(u64 a, u64 b) {
    u64 d; asm("add.rn.f32x2 %0, %1, %2;" : "=l"(d) : "l"(a), "l"(b)); return d;
}

// ---------------- device scratch ----------------
__device__ __align__(16) float g_pa[N_NODES * 16];
__device__ __align__(16) float g_pb[N_NODES * 16];
__device__ __align__(16) float g_msga[N_NODES * 16];
__device__ __align__(16) float g_msgb[N_NODES * 16];

// ============ Kernel A: zero accumulators + per-node precompute ============
__global__ __launch_bounds__(256) void prep_kernel(const float* __restrict__ na,
                                                   const float* __restrict__ nb,
                                                   const float* __restrict__ We1,
                                                   const float* __restrict__ be1) {
    __shared__ __align__(16) float sw[32 * 16];
    __shared__ __align__(16) float sb[16];

    const int b    = blockIdx.x;
    const bool isA = (b < 16);
    const int bb   = isA ? b : b - 16;
    const int tid  = threadIdx.x;

    reinterpret_cast<float2*>(sw)[tid] =
        reinterpret_cast<const float2*>(We1 + (isA ? 0 : 512))[tid];
    if (tid < 16) sb[tid] = isA ? be1[tid] : 0.0f;

    reinterpret_cast<float4*>((isA ? g_msga : g_msgb) + bb * 1024)[tid] =
        make_float4(0.f, 0.f, 0.f, 0.f);
    __syncthreads();

    const int node = bb * 64 + (tid >> 2);
    const int cg   = (tid & 3) * 4;

    const float* row = (isA ? na : nb) + node * 32;
    float x[32];
#pragma unroll
    for (int u = 0; u < 8; u++) {
        float4 v = reinterpret_cast<const float4*>(row)[u];
        x[u * 4 + 0] = v.x; x[u * 4 + 1] = v.y; x[u * 4 + 2] = v.z; x[u * 4 + 3] = v.w;
    }

    float4 acc = *reinterpret_cast<const float4*>(&sb[cg]);
#pragma unroll
    for (int k = 0; k < 32; k++) {
        const float xs = x[k];
        float4 w = *reinterpret_cast<const float4*>(&sw[k * 16 + cg]);
        acc.x = fmaf(xs, w.x, acc.x);
        acc.y = fmaf(xs, w.y, acc.y);
        acc.z = fmaf(xs, w.z, acc.z);
        acc.w = fmaf(xs, w.w, acc.w);
    }

    float* dst = (isA ? g_pa : g_pb) + node * 16 + cg;
    *reinterpret_cast<float4*>(dst) = acc;
}

// Butterfly channel-merging reduction: 16 channels x 32 lanes in 16 shfls.
__device__ __forceinline__ int chan16(int lane) {
    return ((lane & 1) ? 8 : 0) | ((lane & 2) ? 4 : 0) |
           ((lane & 4) ? 2 : 0) | ((lane & 8) ? 1 : 0);
}

__device__ __forceinline__ float warp_reduce16(float* v, int lane) {
    const unsigned FULL = 0xffffffffu;
    {
        bool hi = (lane & 1);
#pragma unroll
        for (int k = 0; k < 8; k++) {
            float send  = hi ? v[k] : v[k + 8];
            float other = __shfl_xor_sync(FULL, send, 1);
            v[k] = (hi ? v[k + 8] : v[k]) + other;
        }
    }
    {
        bool hi = (lane & 2);
#pragma unroll
        for (int k = 0; k < 4; k++) {
            float send  = hi ? v[k] : v[k + 4];
            float other = __shfl_xor_sync(FULL, send, 2);
            v[k] = (hi ? v[k + 4] : v[k]) + other;
        }
    }
    {
        bool hi = (lane & 4);
#pragma unroll
        for (int k = 0; k < 2; k++) {
            float send  = hi ? v[k] : v[k + 2];
            float other = __shfl_xor_sync(FULL, send, 4);
            v[k] = (hi ? v[k + 2] : v[k]) + other;
        }
    }
    {
        bool hi = (lane & 8);
        float send  = hi ? v[0] : v[1];
        float other = __shfl_xor_sync(FULL, send, 8);
        v[0] = (hi ? v[1] : v[0]) + other;
    }
    v[0] += __shfl_xor_sync(FULL, v[0], 16);
    return v[0];
}

// ============ Kernel B: edge MLP + fused message aggregation ============
// ONLY change vs R5: __launch_bounds__(128) — no min-blocks clause, so the
// register budget is 255 and ptxas must not spill the hot loop.
__global__ __launch_bounds__(128) void edge_kernel(const float* __restrict__ edges,
                                                   const float* __restrict__ We1,
                                                   const float* __restrict__ We2,
                                                   const float* __restrict__ be2,
                                                   float* __restrict__ out_e) {
    __shared__ __align__(16) float s_w1[32 * 16];
    __shared__ __align__(16) float s_w2[16 * 16];
    __shared__ __align__(16) float s_pa[8 * 16];
    __shared__ __align__(16) float s_be2[16];

    const int tid  = threadIdx.x;
    const int lane = tid & 31;
    const int j    = blockIdx.x * 128 + tid;
    const int i0   = blockIdx.y * 8;

    reinterpret_cast<float4*>(s_w1)[tid] =
        reinterpret_cast<const float4*>(We1 + 64 * 16)[tid];
    if (tid < 64) {
        reinterpret_cast<float4*>(s_w2)[tid] = reinterpret_cast<const float4*>(We2)[tid];
    } else if (tid < 96) {
        reinterpret_cast<float4*>(s_pa)[tid - 64] =
            reinterpret_cast<const float4*>(g_pa + i0 * 16)[tid - 64];
    } else if (tid < 100) {
        reinterpret_cast<float4*>(s_be2)[tid - 96] =
            reinterpret_cast<const float4*>(be2)[tid - 96];
    }

    u64 pb2[8];
    {
        const float4* p4 = reinterpret_cast<const float4*>(g_pb + j * 16);
#pragma unroll
        for (int u = 0; u < 4; u++) {
            float4 v = p4[u];
            pb2[2 * u]     = pack2(v.x, v.y);
            pb2[2 * u + 1] = pack2(v.z, v.w);
        }
    }

    float msgb[16];
#pragma unroll
    for (int c = 0; c < 16; c++) msgb[c] = 0.0f;

    __syncthreads();

#pragma unroll 1
    for (int ir = 0; ir < 8; ir++) {
        const int i = i0 + ir;
        const float4* xp = reinterpret_cast<const float4*>(edges + ((size_t)i * 1024 + j) * 32);

        u64 h2[8];
        {
            const ulonglong2* par = reinterpret_cast<const ulonglong2*>(&s_pa[ir * 16]);
#pragma unroll
            for (int q = 0; q < 4; q++) {
                ulonglong2 pa = par[q];
                h2[2 * q]     = add2(pa.x, pb2[2 * q]);
                h2[2 * q + 1] = add2(pa.y, pb2[2 * q + 1]);
            }
        }

#pragma unroll
        for (int half = 0; half < 2; half++) {
            float4 xv[4];
#pragma unroll
            for (int u = 0; u < 4; u++) xv[u] = xp[half * 4 + u];
#pragma unroll
            for (int u = 0; u < 4; u++) {
                const float4 v = xv[u];
#pragma unroll
                for (int kk = 0; kk < 4; kk++) {
                    const float xs = (kk == 0) ? v.x : (kk == 1) ? v.y : (kk == 2) ? v.z : v.w;
                    const u64 xs2 = pack2(xs, xs);
                    const ulonglong2* w =
                        reinterpret_cast<const ulonglong2*>(&s_w1[((half * 4 + u) * 4 + kk) * 16]);
#pragma unroll
                    for (int q = 0; q < 4; q++) {
                        ulonglong2 wq = w[q];
                        h2[2 * q]     = ffma2(xs2, wq.x, h2[2 * q]);
                        h2[2 * q + 1] = ffma2(xs2, wq.y, h2[2 * q + 1]);
                    }
                }
            }
        }

        float h[16];
#pragma unroll
        for (int p = 0; p < 8; p++) {
            float lo, hi; unpack2(h2[p], lo, hi);
            h[2 * p]     = fmaxf(lo, 0.0f);
            h[2 * p + 1] = fmaxf(hi, 0.0f);
        }

        u64 e2[8];
        {
            const ulonglong2* bp = reinterpret_cast<const ulonglong2*>(s_be2);
#pragma unroll
            for (int q = 0; q < 4; q++) {
                ulonglong2 bq = bp[q];
                e2[2 * q] = bq.x; e2[2 * q + 1] = bq.y;
            }
        }
#pragma unroll
        for (int k = 0; k < 16; k++) {
            const u64 hs = pack2(h[k], h[k]);
            const ulonglong2* w = reinterpret_cast<const ulonglong2*>(&s_w2[k * 16]);
#pragma unroll
            for (int q = 0; q < 4; q++) {
                ulonglong2 wq = w[q];
                e2[2 * q]     = ffma2(hs, wq.x, e2[2 * q]);
                e2[2 * q + 1] = ffma2(hs, wq.y, e2[2 * q + 1]);
            }
        }

        float e[16];
#pragma unroll
        for (int p = 0; p < 8; p++) {
            float lo, hi; unpack2(e2[p], lo, hi);
            e[2 * p]     = fmaxf(lo, 0.0f);
            e[2 * p + 1] = fmaxf(hi, 0.0f);
        }

        float4* op = reinterpret_cast<float4*>(out_e + ((size_t)i * 1024 + j) * 16);
#pragma unroll
        for (int q = 0; q < 4; q++)
            op[q] = make_float4(e[4 * q], e[4 * q + 1], e[4 * q + 2], e[4 * q + 3]);

#pragma unroll
        for (int c = 0; c < 16; c++) msgb[c] += e[c];

        float total = warp_reduce16(e, lane);
        if (lane < 16) atomicAdd(&g_msga[i * 16 + chan16(lane)], total);
    }

#pragma unroll
    for (int c = 0; c < 16; c++) atomicAdd(&g_msgb[j * 16 + c], msgb[c]);
}

// ============ Kernel C: node MLP (weights + biases via smem) ============
__global__ __launch_bounds__(128) void node_kernel(const float* __restrict__ na,
                                                   const float* __restrict__ nb,
                                                   const float* __restrict__ Wn1,
                                                   const float* __restrict__ bn1,
                                                   const float* __restrict__ Wn2,
                                                   const float* __restrict__ bn2,
                                                   float* __restrict__ out_a,
                                                   float* __restrict__ out_b) {
    __shared__ __align__(16) float s1[48 * 32];
    __shared__ __align__(16) float s2[32 * 32];
    __shared__ __align__(16) float sb1[32];
    __shared__ __align__(16) float sb2[32];

    const int tid = threadIdx.x;
#pragma unroll
    for (int q = 0; q < 3; q++)
        reinterpret_cast<float4*>(s1)[tid * 3 + q] = reinterpret_cast<const float4*>(Wn1)[tid * 3 + q];
#pragma unroll
    for (int q = 0; q < 2; q++)
        reinterpret_cast<float4*>(s2)[tid * 2 + q] = reinterpret_cast<const float4*>(Wn2)[tid * 2 + q];
    if (tid < 32) { sb1[tid] = bn1[tid]; sb2[tid] = bn2[tid]; }
    __syncthreads();

    const int r = blockIdx.x * 128 + tid;
    const float* node;
    const float* msg;
    float* out;
    if (r < N_NODES) {
        node = na + r * 32;  msg = g_msga + r * 16;  out = out_a + r * 32;
    } else {
        int rr = r - N_NODES;
        node = nb + rr * 32; msg = g_msgb + rr * 16; out = out_b + rr * 32;
    }

    float x[48];
#pragma unroll
    for (int u = 0; u < 8; u++) {
        float4 v = reinterpret_cast<const float4*>(node)[u];
        x[u * 4 + 0] = v.x; x[u * 4 + 1] = v.y; x[u * 4 + 2] = v.z; x[u * 4 + 3] = v.w;
    }
#pragma unroll
    for (int u = 0; u < 4; u++) {
        float4 v = reinterpret_cast<const float4*>(msg)[u];
        x[32 + u * 4 + 0] = v.x; x[32 + u * 4 + 1] = v.y;
        x[32 + u * 4 + 2] = v.z; x[32 + u * 4 + 3] = v.w;
    }

    float h[32];
#pragma unroll
    for (int c = 0; c < 32; c++) h[c] = sb1[c];
#pragma unroll
    for (int k = 0; k < 48; k++) {
        const float xs = x[k];
#pragma unroll
        for (int q = 0; q < 8; q++) {
            float4 w = reinterpret_cast<const float4*>(&s1[k * 32])[q];
            h[q * 4 + 0] = fmaf(xs, w.x, h[q * 4 + 0]);
            h[q * 4 + 1] = fmaf(xs, w.y, h[q * 4 + 1]);
            h[q * 4 + 2] = fmaf(xs, w.z, h[q * 4 + 2]);
            h[q * 4 + 3] = fmaf(xs, w.w, h[q * 4 + 3]);
        }
    }
#pragma unroll
    for (int c = 0; c < 32; c++) h[c] = fmaxf(h[c], 0.0f);

    float o[32];
#pragma unroll
    for (int c = 0; c < 32; c++) o[c] = sb2[c];
#pragma unroll
    for (int k = 0; k < 32; k++) {
        const float hs = h[k];
#pragma unroll
        for (int q = 0; q < 8; q++) {
            float4 w = reinterpret_cast<const float4*>(&s2[k * 32])[q];
            o[q * 4 + 0] = fmaf(hs, w.x, o[q * 4 + 0]);
            o[q * 4 + 1] = fmaf(hs, w.y, o[q * 4 + 1]);
            o[q * 4 + 2] = fmaf(hs, w.z, o[q * 4 + 2]);
            o[q * 4 + 3] = fmaf(hs, w.w, o[q * 4 + 3]);
        }
    }
#pragma unroll
    for (int q = 0; q < 8; q++)
        reinterpret_cast<float4*>(out)[q] =
            make_float4(fmaxf(o[q * 4], 0.f), fmaxf(o[q * 4 + 1], 0.f),
                        fmaxf(o[q * 4 + 2], 0.f), fmaxf(o[q * 4 + 3], 0.f));
}

// ============ launch ============
extern "C" void kernel_launch(void* const* d_in, const int* in_sizes, int n_in,
                              void* d_out, int out_size) {
    const float* edges = (const float*)d_in[0];
    const float* na    = (const float*)d_in[1];
    const float* nb    = (const float*)d_in[2];
    const float* We1   = (const float*)d_in[3];
    const float* be1   = (const float*)d_in[4];
    const float* We2   = (const float*)d_in[5];
    const float* be2   = (const float*)d_in[6];
    const float* Wn1   = (const float*)d_in[7];
    const float* bn1   = (const float*)d_in[8];
    const float* Wn2   = (const float*)d_in[9];
    const float* bn2   = (const float*)d_in[10];

    float* out_e = (float*)d_out;
    float* out_a = out_e + (size_t)1024 * 1024 * 16;
    float* out_b = out_a + 1024 * 32;

    prep_kernel<<<32, 256>>>(na, nb, We1, be1);

    dim3 grid(8, 128);
    edge_kernel<<<grid, 128>>>(edges, We1, We2, be2, out_e);

    node_kernel<<<16, 128>>>(na, nb, Wn1, bn1, Wn2, bn2, out_a, out_b);
}

// round 7
// speedup vs baseline: 12.3035x; 12.3035x over previous
#include <cuda_runtime.h>
#include <cuda_bf16.h>

#define N_NODES 1024

typedef unsigned long long u64;

// ---------------- packed f32x2 helpers (sm_103a) ----------------
__device__ __forceinline__ u64 pack2(float lo, float hi) {
    u64 r; asm("mov.b64 %0, {%1, %2};" : "=l"(r) : "f"(lo), "f"(hi)); return r;
}
__device__ __forceinline__ void unpack2(u64 v, float& lo, float& hi) {
    asm("mov.b64 {%0, %1}, %2;" : "=f"(lo), "=f"(hi) : "l"(v));
}
__device__ __forceinline__ u64 ffma2(u64 a, u64 b, u64 c) {
    u64 d; asm("fma.rn.f32x2 %0, %1, %2, %3;" : "=l"(d) : "l"(a), "l"(b), "l"(c)); return d;
}

// ---------------- constant weights (PROVEN R3 path: uniform LDC) ----------------
__constant__ float cWe1[96 * 16];
__constant__ float cbe1[16];
__constant__ float cWe2[16 * 16];
__constant__ float cbe2[16];
__constant__ float cWn1[48 * 32];
__constant__ float cbn1[32];
__constant__ float cWn2[32 * 32];
__constant__ float cbn2[32];

// ---------------- device scratch ----------------
__device__ __align__(16) float g_pa[N_NODES * 16];
__device__ __align__(16) float g_pb[N_NODES * 16];
__device__ __align__(16) float g_msga[N_NODES * 16];
__device__ __align__(16) float g_msgb[N_NODES * 16];

// ============ Kernel A: zero accumulators + per-node precompute ============
__global__ __launch_bounds__(256) void prep_kernel(const float* __restrict__ na,
                                                   const float* __restrict__ nb) {
    const int b    = blockIdx.x;
    const bool isA = (b < 16);
    const int bb   = isA ? b : b - 16;
    const int tid  = threadIdx.x;

    reinterpret_cast<float4*>((isA ? g_msga : g_msgb) + bb * 1024)[tid] =
        make_float4(0.f, 0.f, 0.f, 0.f);

    const int node = bb * 64 + (tid >> 2);
    const int cgq  = (tid & 3);            // channel quad 0..3 (compile-time unrollable below)

    const float* row = (isA ? na : nb) + node * 32;
    float x[32];
#pragma unroll
    for (int u = 0; u < 8; u++) {
        float4 v = reinterpret_cast<const float4*>(row)[u];
        x[u * 4 + 0] = v.x; x[u * 4 + 1] = v.y; x[u * 4 + 2] = v.z; x[u * 4 + 3] = v.w;
    }

    // compute all 16 channels (uniform LDC indices), keep only our quad
    float acc[16];
#pragma unroll
    for (int c = 0; c < 16; c++) acc[c] = isA ? cbe1[c] : 0.0f;
    const int base = isA ? 0 : 32;
#pragma unroll
    for (int k = 0; k < 32; k++) {
        const float xs = x[k];
#pragma unroll
        for (int c = 0; c < 16; c++)
            acc[c] = fmaf(xs, cWe1[(base + k) * 16 + c], acc[c]);
    }

    float* dst = (isA ? g_pa : g_pb) + node * 16 + cgq * 4;
    float4 o;
    o.x = acc[cgq * 4 + 0]; o.y = acc[cgq * 4 + 1];
    o.z = acc[cgq * 4 + 2]; o.w = acc[cgq * 4 + 3];
    *reinterpret_cast<float4*>(dst) = o;
}

// Butterfly channel-merging reduction: 16 channels x 32 lanes in 16 shfls.
__device__ __forceinline__ int chan16(int lane) {
    return ((lane & 1) ? 8 : 0) | ((lane & 2) ? 4 : 0) |
           ((lane & 4) ? 2 : 0) | ((lane & 8) ? 1 : 0);
}

__device__ __forceinline__ float warp_reduce16(float* v, int lane) {
    const unsigned FULL = 0xffffffffu;
    {
        bool hi = (lane & 1);
#pragma unroll
        for (int k = 0; k < 8; k++) {
            float send  = hi ? v[k] : v[k + 8];
            float other = __shfl_xor_sync(FULL, send, 1);
            v[k] = (hi ? v[k + 8] : v[k]) + other;
        }
    }
    {
        bool hi = (lane & 2);
#pragma unroll
        for (int k = 0; k < 4; k++) {
            float send  = hi ? v[k] : v[k + 4];
            float other = __shfl_xor_sync(FULL, send, 2);
            v[k] = (hi ? v[k + 4] : v[k]) + other;
        }
    }
    {
        bool hi = (lane & 4);
#pragma unroll
        for (int k = 0; k < 2; k++) {
            float send  = hi ? v[k] : v[k + 2];
            float other = __shfl_xor_sync(FULL, send, 4);
            v[k] = (hi ? v[k + 2] : v[k]) + other;
        }
    }
    {
        bool hi = (lane & 8);
        float send  = hi ? v[0] : v[1];
        float other = __shfl_xor_sync(FULL, send, 8);
        v[0] = (hi ? v[1] : v[0]) + other;
    }
    v[0] += __shfl_xor_sync(FULL, v[0], 16);
    return v[0];
}

// ============ Kernel B: edge MLP + fused message aggregation ============
// R3 compute core (LDC weights, f32x2, 2 i-rows per iter) + NEW: edge rows
// staged through padded smem with coalesced LDG (kills the 32-line-per-LDG
// wavefront explosion of the AoS direct loads).
#define ROWPAD 36   // floats per staged row (32 data + 4 pad) -> <=4-way LDS conflicts
__global__ __launch_bounds__(128) void edge_kernel(const float* __restrict__ edges,
                                                   float* __restrict__ out_e) {
    __shared__ __align__(16) float s_in[2 * 128 * ROWPAD];  // 2 rows x 128 j
    __shared__ float s_pa[8 * 16];

    const int tid  = threadIdx.x;
    const int lane = tid & 31;
    const int j0   = blockIdx.x * 128;
    const int j    = j0 + tid;
    const int i0   = blockIdx.y * 8;

    s_pa[tid] = g_pa[i0 * 16 + tid];   // 128 floats, 128 threads

    const u64* cWe1p = reinterpret_cast<const u64*>(cWe1);
    const u64* cWe2p = reinterpret_cast<const u64*>(cWe2);

    // pb packed channel pairs (persistent)
    u64 pb2[8];
    {
        const float4* p4 = reinterpret_cast<const float4*>(g_pb + j * 16);
#pragma unroll
        for (int u = 0; u < 4; u++) {
            float4 v = p4[u];
            pb2[2 * u]     = pack2(v.x, v.y);
            pb2[2 * u + 1] = pack2(v.z, v.w);
        }
    }
    u64 be2p[8];
#pragma unroll
    for (int p = 0; p < 8; p++) be2p[p] = pack2(cbe2[2 * p], cbe2[2 * p + 1]);

    float msgb[16];
#pragma unroll
    for (int c = 0; c < 16; c++) msgb[c] = 0.0f;

#pragma unroll 1
    for (int it = 0; it < 4; it++) {
        const int r0 = it * 2;
        const int i  = i0 + r0;

        __syncthreads();   // previous iteration's reads of s_in are done

        // ---- stage rows i, i+1: coalesced LDG.128 -> padded smem rows ----
#pragma unroll
        for (int rr = 0; rr < 2; rr++) {
            const float4* src =
                reinterpret_cast<const float4*>(edges + ((size_t)(i + rr) * 1024 + j0) * 32);
            float* dstbase = s_in + rr * 128 * ROWPAD;
#pragma unroll
            for (int q = 0; q < 8; q++) {
                int g   = q * 128 + tid;     // 0..1023 (float4 units, coalesced)
                int row = g >> 3;            // j within tile
                int kk  = g & 7;             // float4 chunk within row
                float4 v = src[g];
                *reinterpret_cast<float4*>(dstbase + row * ROWPAD + kk * 4) = v;
            }
        }
        __syncthreads();

        // ---- compute 2 rows (R3 core) ----
        const float* myrow0 = s_in + tid * ROWPAD;
        const float* myrow1 = s_in + 128 * ROWPAD + tid * ROWPAD;

        u64 h2[2][8];
#pragma unroll
        for (int p = 0; p < 8; p++) {
            h2[0][p] = pack2(s_pa[r0 * 16 + 2 * p], s_pa[r0 * 16 + 2 * p + 1]);
            h2[1][p] = pack2(s_pa[(r0 + 1) * 16 + 2 * p], s_pa[(r0 + 1) * 16 + 2 * p + 1]);
        }
        // add pb via ffma2 with 1.0 trick? simpler: scalar unpack-add once
#pragma unroll
        for (int r = 0; r < 2; r++)
#pragma unroll
            for (int p = 0; p < 8; p++) {
                float alo, ahi, blo, bhi;
                unpack2(h2[r][p], alo, ahi);
                unpack2(pb2[p], blo, bhi);
                h2[r][p] = pack2(alo + blo, ahi + bhi);
            }

#pragma unroll
        for (int u = 0; u < 8; u++) {
            float4 x0 = *reinterpret_cast<const float4*>(myrow0 + u * 4);
            float4 x1 = *reinterpret_cast<const float4*>(myrow1 + u * 4);
#pragma unroll
            for (int kk = 0; kk < 4; kk++) {
                const float xs0 = (kk == 0) ? x0.x : (kk == 1) ? x0.y : (kk == 2) ? x0.z : x0.w;
                const float xs1 = (kk == 0) ? x1.x : (kk == 1) ? x1.y : (kk == 2) ? x1.z : x1.w;
                const u64 a0 = pack2(xs0, xs0);
                const u64 a1 = pack2(xs1, xs1);
                const ulonglong2* w2 =
                    reinterpret_cast<const ulonglong2*>(cWe1p + (64 + u * 4 + kk) * 8);
#pragma unroll
                for (int q = 0; q < 4; q++) {
                    ulonglong2 w = w2[q];
                    h2[0][2 * q]     = ffma2(a0, w.x, h2[0][2 * q]);
                    h2[0][2 * q + 1] = ffma2(a0, w.y, h2[0][2 * q + 1]);
                    h2[1][2 * q]     = ffma2(a1, w.x, h2[1][2 * q]);
                    h2[1][2 * q + 1] = ffma2(a1, w.y, h2[1][2 * q + 1]);
                }
            }
        }

        float h[2][16];
#pragma unroll
        for (int r = 0; r < 2; r++)
#pragma unroll
            for (int p = 0; p < 8; p++) {
                float lo, hi; unpack2(h2[r][p], lo, hi);
                h[r][2 * p]     = fmaxf(lo, 0.0f);
                h[r][2 * p + 1] = fmaxf(hi, 0.0f);
            }

        u64 e2p[2][8];
#pragma unroll
        for (int p = 0; p < 8; p++) { e2p[0][p] = be2p[p]; e2p[1][p] = be2p[p]; }
#pragma unroll
        for (int k = 0; k < 16; k++) {
            const u64 a0 = pack2(h[0][k], h[0][k]);
            const u64 a1 = pack2(h[1][k], h[1][k]);
            const ulonglong2* w2 = reinterpret_cast<const ulonglong2*>(cWe2p + k * 8);
#pragma unroll
            for (int q = 0; q < 4; q++) {
                ulonglong2 w = w2[q];
                e2p[0][2 * q]     = ffma2(a0, w.x, e2p[0][2 * q]);
                e2p[0][2 * q + 1] = ffma2(a0, w.y, e2p[0][2 * q + 1]);
                e2p[1][2 * q]     = ffma2(a1, w.x, e2p[1][2 * q]);
                e2p[1][2 * q + 1] = ffma2(a1, w.y, e2p[1][2 * q + 1]);
            }
        }

#pragma unroll
        for (int r = 0; r < 2; r++) {
            float e[16];
#pragma unroll
            for (int p = 0; p < 8; p++) {
                float lo, hi; unpack2(e2p[r][p], lo, hi);
                e[2 * p]     = fmaxf(lo, 0.0f);
                e[2 * p + 1] = fmaxf(hi, 0.0f);
            }

            float4* op = reinterpret_cast<float4*>(out_e + ((size_t)(i + r) * 1024 + j) * 16);
#pragma unroll
            for (int q = 0; q < 4; q++)
                op[q] = make_float4(e[4 * q], e[4 * q + 1], e[4 * q + 2], e[4 * q + 3]);

#pragma unroll
            for (int c = 0; c < 16; c++) msgb[c] += e[c];

            float total = warp_reduce16(e, lane);
            if (lane < 16) atomicAdd(&g_msga[(i + r) * 16 + chan16(lane)], total);
        }
    }

#pragma unroll
    for (int c = 0; c < 16; c++) atomicAdd(&g_msgb[j * 16 + c], msgb[c]);
}

// ============ Kernel C: node MLP (constant weights, uniform LDC — R3 proven) ============
__global__ __launch_bounds__(256) void node_kernel(const float* __restrict__ na,
                                                   const float* __restrict__ nb,
                                                   float* __restrict__ out_a,
                                                   float* __restrict__ out_b) {
    int r = blockIdx.x * blockDim.x + threadIdx.x;
    if (r >= 2 * N_NODES) return;

    const float* node;
    const float* msg;
    float* out;
    if (r < N_NODES) {
        node = na + r * 32;  msg = g_msga + r * 16;  out = out_a + r * 32;
    } else {
        int rr = r - N_NODES;
        node = nb + rr * 32; msg = g_msgb + rr * 16; out = out_b + rr * 32;
    }

    float x[48];
#pragma unroll
    for (int k = 0; k < 32; k++) x[k] = node[k];
#pragma unroll
    for (int k = 0; k < 16; k++) x[32 + k] = msg[k];

    float h[32];
#pragma unroll
    for (int c = 0; c < 32; c++) h[c] = cbn1[c];
#pragma unroll
    for (int k = 0; k < 48; k++) {
#pragma unroll
        for (int c = 0; c < 32; c++)
            h[c] = fmaf(x[k], cWn1[k * 32 + c], h[c]);
    }
#pragma unroll
    for (int c = 0; c < 32; c++) h[c] = fmaxf(h[c], 0.0f);

    float o[32];
#pragma unroll
    for (int c = 0; c < 32; c++) o[c] = cbn2[c];
#pragma unroll
    for (int k = 0; k < 32; k++) {
#pragma unroll
        for (int c = 0; c < 32; c++)
            o[c] = fmaf(h[k], cWn2[k * 32 + c], o[c]);
    }
#pragma unroll
    for (int c = 0; c < 32; c++) out[c] = fmaxf(o[c], 0.0f);
}

// ============ launch ============
extern "C" void kernel_launch(void* const* d_in, const int* in_sizes, int n_in,
                              void* d_out, int out_size) {
    const float* edges = (const float*)d_in[0];
    const float* na    = (const float*)d_in[1];
    const float* nb    = (const float*)d_in[2];

    cudaMemcpyToSymbolAsync(cWe1, d_in[3], 96 * 16 * sizeof(float), 0, cudaMemcpyDeviceToDevice);
    cudaMemcpyToSymbolAsync(cbe1, d_in[4], 16 * sizeof(float),      0, cudaMemcpyDeviceToDevice);
    cudaMemcpyToSymbolAsync(cWe2, d_in[5], 16 * 16 * sizeof(float), 0, cudaMemcpyDeviceToDevice);
    cudaMemcpyToSymbolAsync(cbe2, d_in[6], 16 * sizeof(float),      0, cudaMemcpyDeviceToDevice);
    cudaMemcpyToSymbolAsync(cWn1, d_in[7], 48 * 32 * sizeof(float), 0, cudaMemcpyDeviceToDevice);
    cudaMemcpyToSymbolAsync(cbn1, d_in[8], 32 * sizeof(float),      0, cudaMemcpyDeviceToDevice);
    cudaMemcpyToSymbolAsync(cWn2, d_in[9], 32 * 32 * sizeof(float), 0, cudaMemcpyDeviceToDevice);
    cudaMemcpyToSymbolAsync(cbn2, d_in[10], 32 * sizeof(float),     0, cudaMemcpyDeviceToDevice);

    float* out_e = (float*)d_out;
    float* out_a = out_e + (size_t)1024 * 1024 * 16;
    float* out_b = out_a + 1024 * 32;

    prep_kernel<<<32, 256>>>(na, nb);

    dim3 grid(8, 128);
    edge_kernel<<<grid, 128>>>(edges, out_e);

    node_kernel<<<8, 256>>>(na, nb, out_a, out_b);
}